// round 8
// baseline (speedup 1.0000x reference)
#include <cuda_runtime.h>
#include <stdint.h>
#include <math.h>

// Problem constants (fixed shapes: scores (128, 4096, 2))
#define NN   4096
#define BSZ  128
#define ENS  2
#define BE   256           // BSZ*ENS
#define KK   32
#define NEGC (-1e30f)
#define HALF_OUT 1048576   // 128*4096*2
#define NCHUNK 32
#define CLEN   128         // NN / NCHUNK
#define NSLICE 8
#define SLEN   512         // NN / NSLICE
#define BK_BLK 128         // backward blocks (2 b each)

// ---------------- scratch (static device memory) ----------------
__device__ float    g_B[(size_t)(NN + 1) * BE * KK]; // B[i][b][j-1]
__device__ float    g_F[(size_t)NN * BE * KK];       // F[i][b][j] (pre-update)
__device__ unsigned g_mask[(size_t)BE * NN];         // inclusion masks [b*NN + i]
__device__ float    g_CE[(size_t)BE * NCHUNK * KK];  // chunk ESPs
__device__ float    g_BD[(size_t)BE * NCHUNK * KK];  // chunk boundary prefixes
__device__ float    g_S[(size_t)NN * BE];            // th + log_ekm1 (unnormalized)
__device__ float    g_T[(size_t)NN * BE];            // transposed theta [i*BE + b]
__device__ float    g_E[(size_t)BE * KK];            // backward state between slices
__device__ float    g_logZ[BE];
__device__ unsigned g_bits[(size_t)BE * (NN / 32)];  // sampled bits

// ---------------- threefry2x32, key = (0, 42) ----------------
__device__ __forceinline__ uint32_t tf_bits(uint32_t lo)
{
    uint32_t x0 = 0u;
    uint32_t x1 = lo;
    const uint32_t ks0 = 0u, ks1 = 42u, ks2 = 0x1BD11BF0u;
    x0 += ks0; x1 += ks1;
#define TFR(r) { x0 += x1; x1 = (x1 << (r)) | (x1 >> (32 - (r))); x1 ^= x0; }
    TFR(13) TFR(15) TFR(26) TFR(6)   x0 += ks1; x1 += ks2 + 1u;
    TFR(17) TFR(29) TFR(16) TFR(24)  x0 += ks2; x1 += ks0 + 2u;
    TFR(13) TFR(15) TFR(26) TFR(6)   x0 += ks0; x1 += ks1 + 3u;
    TFR(17) TFR(29) TFR(16) TFR(24)  x0 += ks1; x1 += ks2 + 4u;
    TFR(13) TFR(15) TFR(26) TFR(6)   x0 += ks2; x1 += ks0 + 5u;
#undef TFR
    return x0 ^ x1;
}

// EXACT logaddexp (libdevice — bitwise path for sampling masks)
__device__ __forceinline__ float logaddexpf32(float x, float y)
{
    float d = x - y;
    return fmaxf(x, y) + log1pf(expf(-fabsf(d)));
}

// Fast logaddexp (marginals path, 1e-3 tolerance)
__device__ __forceinline__ float logaddexp_fast(float x, float y)
{
    float d = x - y;
    return fmaxf(x, y) + __logf(1.0f + __expf(-fabsf(d)));
}

// ---------------- sampler helpers (numerics unchanged) ----------------
__device__ __forceinline__ void samp_word(unsigned m, int ii, unsigned& r, unsigned& w)
{
    unsigned incl = (unsigned)(r > 0) & ((m >> ((r - 1u) & 31u)) & 1u);
    r -= incl;
    w |= incl << ii;
}

__device__ __forceinline__ unsigned samp_block(const uint4* buf, unsigned& r)
{
    unsigned w = 0;
#pragma unroll
    for (int q = 0; q < 8; ++q) {
        uint4 v = buf[q];
        samp_word(v.x, 4 * q + 0, r, w);
        samp_word(v.y, 4 * q + 1, r, w);
        samp_word(v.z, 4 * q + 2, r, w);
        samp_word(v.w, 4 * q + 3, r, w);
    }
    return w;
}

__device__ void run_sampler(int b)
{
    const uint4* mp = reinterpret_cast<const uint4*>(g_mask + (size_t)b * NN);
    unsigned r = KK;
    uint4 A[8], Bb[8];
#pragma unroll
    for (int q = 0; q < 8; ++q) A[q] = mp[q];
    for (int blk = 0; blk < 128; blk += 2) {
#pragma unroll
        for (int q = 0; q < 8; ++q) Bb[q] = mp[(blk + 1) * 8 + q];
        g_bits[(size_t)b * 128 + blk] = samp_block(A, r);
        if (blk + 2 < 128) {
#pragma unroll
            for (int q = 0; q < 8; ++q) A[q] = mp[(blk + 2) * 8 + q];
        }
        g_bits[(size_t)b * 128 + blk + 1] = samp_block(Bb, r);
    }
}

// ---------------- warp-specialized backward scan ----------------
// Chain warp: exact recurrence only. Writes lq rows to a double-buffered smem
// ring (32-step chunks) and g_B rows. Never blocks in steady state.
__device__ void backward_chain(const float* __restrict__ scores, int s,
                               float* smem_lq, volatile int* flagC, volatile int* flagM)
{
    int lane = threadIdx.x & 31;
    int bb = threadIdx.x >> 5;            // 0 or 1
    int b = blockIdx.x * 2 + bb;
    const int bz = b >> 1, e = b & 1;
    const float* thbase = scores + (size_t)bz * (NN * ENS) + e;

    float E;
    if (s == 0) {
        E = NEGC;
        g_B[((size_t)NN * BE + b) * KK + lane] = NEGC;   // init row (i = NN)
    } else {
        E = g_E[(size_t)b * KK + lane];
    }

    int blk_start = 127 - s * 16;
    float thv = thbase[2 * (blk_start * 32 + lane)];

    for (int c = 0; c < 16; ++c) {
        int blk = blk_start - c;
        int base = blk * 32;
        float thv_next = (c < 15) ? thbase[2 * ((blk - 1) * 32 + lane)] : 0.0f;

        if (c >= 2) { while (*flagM < c - 1) { } }      // buffer free?
        float* buf = smem_lq + (size_t)(c & 1) * (32 * 32);

#pragma unroll 8
        for (int ii = 31; ii >= 0; --ii) {
            float th = __shfl_sync(0xffffffffu, thv, ii);
            float Ep = __shfl_up_sync(0xffffffffu, E, 1);
            if (lane == 0) Ep = 0.0f;
            float shifted = Ep + th;
            float Enew = logaddexpf32(E, shifted);       // EXACT
            buf[ii * 32 + lane] = shifted - Enew;        // logq (off-chain)
            E = Enew;
            g_B[((size_t)(base + ii) * BE + b) * KK + lane] = E;
        }
        __threadfence_block();
        __syncwarp();
        if (lane == 0) *flagC = c + 1;
        thv = thv_next;
    }

    if (s == NSLICE - 1) {
        float lz = __shfl_sync(0xffffffffu, E, 31);      // B[0][b][32] = logZ
        if (lane == 0) g_logZ[b] = lz;
    } else {
        g_E[(size_t)b * KK + lane] = E;
    }
}

// Mask warp: threefry + expf + ballot + mask store; slice 7 also runs sampler.
__device__ void backward_mask(int s, const float* smem_lq,
                              volatile int* flagC, volatile int* flagM)
{
    int lane = threadIdx.x & 31;
    int bb = (threadIdx.x >> 5) - 2;
    int b = blockIdx.x * 2 + bb;
    int blk_start = 127 - s * 16;

    for (int c = 0; c < 16; ++c) {
        int blk = blk_start - c;
        int base = blk * 32;
        // inline threefry uniform (bit-identical index i*BE+b), off chain
        uint32_t rb = tf_bits((uint32_t)((base + lane) * BE + b));
        float uv = fmaxf(__uint_as_float((rb >> 9) | 0x3f800000u) - 1.0f, 0.0f);

        while (*flagC < c + 1) { }
        __threadfence_block();
        const float* buf = smem_lq + (size_t)(c & 1) * (32 * 32);

#pragma unroll 8
        for (int ii = 31; ii >= 0; --ii) {
            float lq = buf[ii * 32 + lane];
            float q = expf(fminf(lq, 0.0f));             // EXACT (matches passing kernels)
            float u = __shfl_sync(0xffffffffu, uv, ii);
            unsigned m = __ballot_sync(0xffffffffu, u < q);
            if (lane == 0) g_mask[(size_t)b * NN + base + ii] = m;
        }
        __syncwarp();
        if (lane == 0) *flagM = c + 1;
    }

    if (s == NSLICE - 1 && lane == 0) run_sampler(b);
}

// ---------------- worker pieces (unchanged numerics) ----------------
__device__ void phaseA(const float* __restrict__ scores, int xb)
{
    int lane = threadIdx.x & 31;
    int wid = xb * 4 + (threadIdx.x >> 5);   // 0..8191
    int b = wid >> 5;
    int c = wid & 31;
    const int bz = b >> 1, e = b & 1;
    const float* thbase = scores + (size_t)bz * (NN * ENS) + e;

    float F = (lane == 0) ? 0.0f : NEGC;
    int base0 = c * CLEN;
    for (int blk = 0; blk < CLEN / 32; ++blk) {
        float thv = thbase[2 * (base0 + blk * 32 + lane)];
#pragma unroll 8
        for (int ii = 0; ii < 32; ++ii) {
            float th = __shfl_sync(0xffffffffu, thv, ii);
            float Fp = __shfl_up_sync(0xffffffffu, F, 1);
            if (lane == 0) Fp = NEGC;
            F = logaddexp_fast(F, Fp + th);
        }
    }
    g_CE[((size_t)b * NCHUNK + c) * KK + lane] = F;
}

__device__ void transpose_theta(const float* __restrict__ scores, int xb)
{
    int idx = (xb * 128 + threadIdx.x) * 4;
#pragma unroll
    for (int q = 0; q < 4; ++q, ++idx) {
        int b = idx & (BE - 1);
        int i = idx >> 8;
        g_T[idx] = scores[(size_t)(b >> 1) * (NN * ENS) + i * ENS + (b & 1)];
    }
}

__device__ void merge_chunks(int xb)
{
    int lane = threadIdx.x & 31;
    int b = xb * 4 + (threadIdx.x >> 5);

    float P = (lane == 0) ? 0.0f : NEGC;
    for (int c = 0; c < NCHUNK; ++c) {
        g_BD[((size_t)b * NCHUNK + c) * KK + lane] = P;  // exclusive prefix
        float L = g_CE[((size_t)b * NCHUNK + c) * KK + lane];
        float mx = NEGC;
#pragma unroll
        for (int m = 0; m < 32; ++m) {
            float Pm = __shfl_sync(0xffffffffu, P, m);
            float Lx = __shfl_sync(0xffffffffu, L, (lane - m) & 31);
            if (m <= lane) mx = fmaxf(mx, Pm + Lx);
        }
        float sum = 0.0f;
#pragma unroll
        for (int m = 0; m < 32; ++m) {
            float Pm = __shfl_sync(0xffffffffu, P, m);
            float Lx = __shfl_sync(0xffffffffu, L, (lane - m) & 31);
            if (m <= lane) sum += __expf(Pm + Lx - mx);
        }
        P = mx + __logf(sum);
    }
}

__device__ void phaseC_storeF(const float* __restrict__ scores, int xb)
{
    int lane = threadIdx.x & 31;
    int wid = xb * 4 + (threadIdx.x >> 5);
    int b = wid >> 5;
    int c = wid & 31;
    const int bz = b >> 1, e = b & 1;
    const float* thbase = scores + (size_t)bz * (NN * ENS) + e;

    float F = g_BD[((size_t)b * NCHUNK + c) * KK + lane];
    int base0 = c * CLEN;
    for (int blk = 0; blk < CLEN / 32; ++blk) {
        float thv = thbase[2 * (base0 + blk * 32 + lane)];
#pragma unroll 8
        for (int ii = 0; ii < 32; ++ii) {
            int i = base0 + blk * 32 + ii;
            g_F[((size_t)i * BE + b) * KK + lane] = F;
            float th = __shfl_sync(0xffffffffu, thv, ii);
            float Fp = __shfl_up_sync(0xffffffffu, F, 1);
            if (lane == 0) Fp = NEGC;
            F = logaddexp_fast(F, Fp + th);
        }
    }
}

__device__ void comb_band(int xb, int rowbase)
{
    int tid = xb * 128 + threadIdx.x;
    int b = tid & (BE - 1);
    int i = rowbase + (tid >> 8);

    const float4* Fr = reinterpret_cast<const float4*>(&g_F[((size_t)i * BE + b) * KK]);
    const float4* Br = reinterpret_cast<const float4*>(&g_B[((size_t)(i + 1) * BE + b) * KK]);

    float Fv[32], Bv[32];
#pragma unroll
    for (int q = 0; q < 8; ++q) {
        float4 f4 = Fr[q];
        Fv[4 * q + 0] = f4.x; Fv[4 * q + 1] = f4.y; Fv[4 * q + 2] = f4.z; Fv[4 * q + 3] = f4.w;
        float4 b4 = Br[q];
        Bv[4 * q + 0] = b4.x; Bv[4 * q + 1] = b4.y; Bv[4 * q + 2] = b4.z; Bv[4 * q + 3] = b4.w;
    }

    float comb[32];
#pragma unroll
    for (int j = 0; j < 32; ++j) {
        float bc = (j == 31) ? 0.0f : Bv[30 - j];   // B[i+1][31-j]; col 0 == 0
        comb[j] = Fv[j] + bc;
    }
    float mx = comb[0];
#pragma unroll
    for (int j = 1; j < 32; ++j) mx = fmaxf(mx, comb[j]);
    float sum = 0.0f;
#pragma unroll
    for (int j = 0; j < 32; ++j) sum += __expf(comb[j] - mx);

    g_S[(size_t)i * BE + b] = g_T[(size_t)i * BE + b] + mx + __logf(sum);
}

// ---------------- sliced fused kernel ----------------
__global__ void k_slice(const float* __restrict__ scores, int s)
{
    __shared__ float s_lq[2][2][32 * 32];   // [bb][buf][step*32+lane]
    __shared__ int   s_flag[2][2];          // [bb][0=chain, 1=mask]

    if (blockIdx.x < BK_BLK) {
        if (threadIdx.x < 4) s_flag[threadIdx.x >> 1][threadIdx.x & 1] = 0;
        __syncthreads();
        int wid = threadIdx.x >> 5;
        if (wid < 2) {
            backward_chain(scores, s, s_lq[wid][0],
                           (volatile int*)&s_flag[wid][0], (volatile int*)&s_flag[wid][1]);
        } else {
            backward_mask(s, s_lq[wid - 2][0],
                          (volatile int*)&s_flag[wid - 2][0], (volatile int*)&s_flag[wid - 2][1]);
        }
        return;
    }

    int xb = blockIdx.x - BK_BLK;
    if (s == 0) {
        if (xb < 2048) phaseA(scores, xb);
        else transpose_theta(scores, xb - 2048);
    } else if (s == 1) {
        merge_chunks(xb);
    } else if (s == 2) {
        phaseC_storeF(scores, xb);
    } else {
        // comb bands chase the backward scan down:
        // s=3 -> rows [2560,4096); s=4..7 -> [4096-512s, 4096-512(s-1))
        int rowbase = (s == 3) ? 2560 : (NN - SLEN * s);
        comb_band(xb, rowbase);
    }
}

// ---------------- tail: last comb band only ----------------
__global__ void k_tail()
{
    comb_band(blockIdx.x, 0);   // rows [0, 512)
}

// ---------------- finalize ----------------
__global__ void k_final(float* __restrict__ out)
{
    int tid = blockIdx.x * blockDim.x + threadIdx.x;  // 0 .. 2^20-1
    int bz = tid >> 13;
    int rem = tid & 8191;
    int n = rem >> 1;
    int e = rem & 1;
    int be = bz * ENS + e;
    float s = (float)((g_bits[(size_t)be * (NN / 32) + (n >> 5)] >> (n & 31)) & 1u);
    float m = __expf(g_S[(size_t)n * BE + be] - g_logZ[be]);
    out[tid] = (s - m) + m;
    out[HALF_OUT + tid] = m;
}

extern "C" void kernel_launch(void* const* d_in, const int* in_sizes, int n_in,
                              void* d_out, int out_size)
{
    const float* scores = (const float*)d_in[0];
    float* out = (float*)d_out;
    (void)in_sizes; (void)n_in; (void)out_size;

    k_slice<<<BK_BLK + 2048 + 2048, 128>>>(scores, 0);  // backward + phaseA + transpose
    k_slice<<<BK_BLK + 64,          128>>>(scores, 1);  // backward + merge
    k_slice<<<BK_BLK + 2048,        128>>>(scores, 2);  // backward + phaseC (store F)
    k_slice<<<BK_BLK + 3072,        128>>>(scores, 3);  // backward + comb [2560,4096)
    k_slice<<<BK_BLK + 1024,        128>>>(scores, 4);  // backward + comb [2048,2560)
    k_slice<<<BK_BLK + 1024,        128>>>(scores, 5);  // backward + comb [1536,2048)
    k_slice<<<BK_BLK + 1024,        128>>>(scores, 6);  // backward + comb [1024,1536)
    k_slice<<<BK_BLK + 1024,        128>>>(scores, 7);  // backward + comb [512,1024) + sampler
    k_tail<<<1024, 128>>>();                            // comb [0,512)
    k_final<<<2048, 512>>>(out);
}

// round 9
// speedup vs baseline: 1.0385x; 1.0385x over previous
#include <cuda_runtime.h>
#include <stdint.h>
#include <math.h>

// Problem constants (fixed shapes: scores (128, 4096, 2))
#define NN   4096
#define BSZ  128
#define ENS  2
#define BE   256           // BSZ*ENS
#define KK   32
#define NEGC (-1e30f)
#define HALF_OUT 1048576   // 128*4096*2
#define NCHUNK 32
#define CLEN   128         // NN / NCHUNK
#define NSLICE 8
#define SLEN   512         // NN / NSLICE

// ---------------- scratch (static device memory) ----------------
__device__ float    g_B[(size_t)(NN + 1) * BE * KK]; // B[i][b][j-1]
__device__ float    g_F[(size_t)NN * BE * KK];       // F[i][b][j] (pre-update)
__device__ unsigned g_mask[(size_t)BE * NN];         // inclusion masks [b*NN + i]
__device__ float    g_CE[(size_t)BE * NCHUNK * KK];  // chunk ESPs
__device__ float    g_BD[(size_t)BE * NCHUNK * KK];  // chunk boundary prefixes
__device__ float    g_S[(size_t)NN * BE];            // th + log_ekm1 (unnormalized)
__device__ float    g_T[(size_t)NN * BE];            // transposed theta [i*BE + b]
__device__ float    g_E[(size_t)BE * KK];            // backward state between slices
__device__ float    g_logZ[BE];
__device__ unsigned g_bits[(size_t)BE * (NN / 32)];  // sampled bits
// sampler chunk-function tables: per (b, chunk c of 128, r_in=lane+1)
__device__ unsigned g_sampBits[(size_t)BE * 128 * 32];
__device__ unsigned g_sampMap[(size_t)BE * 128 * 32];

// ---------------- threefry2x32, key = (0, 42) ----------------
__device__ __forceinline__ uint32_t tf_bits(uint32_t lo)
{
    uint32_t x0 = 0u;
    uint32_t x1 = lo;
    const uint32_t ks0 = 0u, ks1 = 42u, ks2 = 0x1BD11BF0u;
    x0 += ks0; x1 += ks1;
#define TFR(r) { x0 += x1; x1 = (x1 << (r)) | (x1 >> (32 - (r))); x1 ^= x0; }
    TFR(13) TFR(15) TFR(26) TFR(6)   x0 += ks1; x1 += ks2 + 1u;
    TFR(17) TFR(29) TFR(16) TFR(24)  x0 += ks2; x1 += ks0 + 2u;
    TFR(13) TFR(15) TFR(26) TFR(6)   x0 += ks0; x1 += ks1 + 3u;
    TFR(17) TFR(29) TFR(16) TFR(24)  x0 += ks1; x1 += ks2 + 4u;
    TFR(13) TFR(15) TFR(26) TFR(6)   x0 += ks2; x1 += ks0 + 5u;
#undef TFR
    return x0 ^ x1;
}

// EXACT logaddexp (libdevice — bitwise path for sampling masks)
__device__ __forceinline__ float logaddexpf32(float x, float y)
{
    float d = x - y;
    return fmaxf(x, y) + log1pf(expf(-fabsf(d)));
}

// Fast logaddexp (marginals path, 1e-3 tolerance)
__device__ __forceinline__ float logaddexp_fast(float x, float y)
{
    float d = x - y;
    return fmaxf(x, y) + __logf(1.0f + __expf(-fabsf(d)));
}

// ---------------- backward slice (exact chain, DEFERRED ballots) ----------------
__device__ void backward_slice(const float* __restrict__ scores, int s)
{
    int lane = threadIdx.x & 31;
    int b = blockIdx.x * 4 + (threadIdx.x >> 5);
    const int bz = b >> 1, e = b & 1;
    const float* thbase = scores + (size_t)bz * (NN * ENS) + e;

    float E;
    if (s == 0) {
        E = NEGC;
        g_B[((size_t)NN * BE + b) * KK + lane] = NEGC;   // init row (i = NN)
    } else {
        E = g_E[(size_t)b * KK + lane];
    }

    int blk_hi = (NN / 32) - 16 * s;        // exclusive
    int blk_lo = blk_hi - 16;

    // prefetch theta for the first block of this slice
    float thv = thbase[2 * ((blk_hi - 1) * 32 + lane)];

    for (int blk = blk_hi - 1; blk >= blk_lo; --blk) {
        int base = blk * 32;
        float thv_next = (blk > blk_lo) ? thbase[2 * ((blk - 1) * 32 + lane)] : 0.0f;
        // inline threefry uniform (bit-identical to jax.random.uniform, index i*BE+b)
        uint32_t rb = tf_bits((uint32_t)((base + lane) * BE + b));
        float uv = fmaxf(__uint_as_float((rb >> 9) | 0x3f800000u) - 1.0f, 0.0f);

#pragma unroll
        for (int g8 = 3; g8 >= 0; --g8) {
            float lq[8];
            // chain segment: 8 exact steps; ballots deferred (off critical path)
#pragma unroll
            for (int t = 7; t >= 0; --t) {
                int ii = g8 * 8 + t;
                float th = __shfl_sync(0xffffffffu, thv, ii);
                float Ep = __shfl_up_sync(0xffffffffu, E, 1);
                if (lane == 0) Ep = 0.0f;
                float shifted = Ep + th;
                float Enew = logaddexpf32(E, shifted);
                lq[t] = shifted - Enew;       // logq, buffered
                E = Enew;
                g_B[((size_t)(base + ii) * BE + b) * KK + lane] = E;
            }
            // deferred mask generation: 8 independent expf+ballot, pipelined
#pragma unroll
            for (int t = 7; t >= 0; --t) {
                int ii = g8 * 8 + t;
                float u = __shfl_sync(0xffffffffu, uv, ii);
                float q = expf(fminf(lq[t], 0.0f));
                unsigned m = __ballot_sync(0xffffffffu, u < q);
                if (lane == 0) g_mask[(size_t)b * NN + base + ii] = m;
            }
        }
        thv = thv_next;
    }

    if (s < NSLICE - 1) {
        g_E[(size_t)b * KK + lane] = E;
    } else {
        float lz = __shfl_sync(0xffffffffu, E, 31);   // B[0][b][32] = logZ
        if (lane == 0) g_logZ[b] = lz;
    }
}

// ---------------- sampler chunk-function evaluation ----------------
// One warp per (b, chunk): lane holds hypothesis r_in = lane+1, walks 32 mask
// words (shared via shfl broadcast), records resulting bits-word and r_out.
// Bit-exact with the sequential sampler (same per-step update).
__device__ void samp_chunk(int xb, int band)
{
    int lane = threadIdx.x & 31;
    int item = xb * 4 + (threadIdx.x >> 5);   // 0..4095
    int b = item >> 4;
    int c = (112 - 16 * band) + (item & 15);  // chunk index 0..127

    unsigned mv = g_mask[(size_t)b * NN + c * 32 + lane];  // coalesced
    unsigned r = (unsigned)(lane + 1);
    unsigned w = 0u;
#pragma unroll
    for (int ii = 0; ii < 32; ++ii) {
        unsigned m = __shfl_sync(0xffffffffu, mv, ii);
        unsigned incl = r ? ((m >> (r - 1u)) & 1u) : 0u;
        r -= incl;
        w |= incl << ii;
    }
    g_sampBits[((size_t)b * 128 + c) * 32 + lane] = w;
    g_sampMap[((size_t)b * 128 + c) * 32 + lane] = r;
}

// ---------------- sampler composition: thread the real state ----------------
__global__ void k_comp()
{
    int lane = threadIdx.x & 31;
    int b = blockIdx.x * 4 + (threadIdx.x >> 5);
    const unsigned* mp = &g_sampMap[(size_t)b * 128 * 32];
    const unsigned* bp = &g_sampBits[(size_t)b * 128 * 32];

    unsigned r = KK;   // warp-uniform
#pragma unroll 4
    for (int c = 0; c < 128; ++c) {
        unsigned mapv = mp[c * 32 + lane];   // loads independent of r (pipelined)
        unsigned bitv = bp[c * 32 + lane];
        unsigned idx = r ? (r - 1u) : 0u;
        unsigned bits = __shfl_sync(0xffffffffu, bitv, idx);
        unsigned rn   = __shfl_sync(0xffffffffu, mapv, idx);
        if (!r) { bits = 0u; rn = 0u; }
        if (lane == 0) g_bits[(size_t)b * 128 + c] = bits;
        r = rn;
    }
}

// ---------------- worker pieces (unchanged numerics) ----------------
__device__ void phaseA(const float* __restrict__ scores, int xb)
{
    int lane = threadIdx.x & 31;
    int wid = xb * 4 + (threadIdx.x >> 5);   // 0..8191
    int b = wid >> 5;
    int c = wid & 31;
    const int bz = b >> 1, e = b & 1;
    const float* thbase = scores + (size_t)bz * (NN * ENS) + e;

    float F = (lane == 0) ? 0.0f : NEGC;
    int base0 = c * CLEN;
    for (int blk = 0; blk < CLEN / 32; ++blk) {
        float thv = thbase[2 * (base0 + blk * 32 + lane)];
#pragma unroll 8
        for (int ii = 0; ii < 32; ++ii) {
            float th = __shfl_sync(0xffffffffu, thv, ii);
            float Fp = __shfl_up_sync(0xffffffffu, F, 1);
            if (lane == 0) Fp = NEGC;
            F = logaddexp_fast(F, Fp + th);
        }
    }
    g_CE[((size_t)b * NCHUNK + c) * KK + lane] = F;
}

__device__ void transpose_theta(const float* __restrict__ scores, int xb)
{
    int idx = (xb * 128 + threadIdx.x) * 4;
#pragma unroll
    for (int q = 0; q < 4; ++q, ++idx) {
        int b = idx & (BE - 1);
        int i = idx >> 8;
        g_T[idx] = scores[(size_t)(b >> 1) * (NN * ENS) + i * ENS + (b & 1)];
    }
}

__device__ void merge_chunks(int xb)
{
    int lane = threadIdx.x & 31;
    int b = xb * 4 + (threadIdx.x >> 5);

    float P = (lane == 0) ? 0.0f : NEGC;
    for (int c = 0; c < NCHUNK; ++c) {
        g_BD[((size_t)b * NCHUNK + c) * KK + lane] = P;  // exclusive prefix
        float L = g_CE[((size_t)b * NCHUNK + c) * KK + lane];
        float mx = NEGC;
#pragma unroll
        for (int m = 0; m < 32; ++m) {
            float Pm = __shfl_sync(0xffffffffu, P, m);
            float Lx = __shfl_sync(0xffffffffu, L, (lane - m) & 31);
            if (m <= lane) mx = fmaxf(mx, Pm + Lx);
        }
        float sum = 0.0f;
#pragma unroll
        for (int m = 0; m < 32; ++m) {
            float Pm = __shfl_sync(0xffffffffu, P, m);
            float Lx = __shfl_sync(0xffffffffu, L, (lane - m) & 31);
            if (m <= lane) sum += __expf(Pm + Lx - mx);
        }
        P = mx + __logf(sum);
    }
}

__device__ void phaseC_storeF(const float* __restrict__ scores, int xb)
{
    int lane = threadIdx.x & 31;
    int wid = xb * 4 + (threadIdx.x >> 5);
    int b = wid >> 5;
    int c = wid & 31;
    const int bz = b >> 1, e = b & 1;
    const float* thbase = scores + (size_t)bz * (NN * ENS) + e;

    float F = g_BD[((size_t)b * NCHUNK + c) * KK + lane];
    int base0 = c * CLEN;
    for (int blk = 0; blk < CLEN / 32; ++blk) {
        float thv = thbase[2 * (base0 + blk * 32 + lane)];
#pragma unroll 8
        for (int ii = 0; ii < 32; ++ii) {
            int i = base0 + blk * 32 + ii;
            g_F[((size_t)i * BE + b) * KK + lane] = F;
            float th = __shfl_sync(0xffffffffu, thv, ii);
            float Fp = __shfl_up_sync(0xffffffffu, F, 1);
            if (lane == 0) Fp = NEGC;
            F = logaddexp_fast(F, Fp + th);
        }
    }
}

__device__ void comb_band(int xb, int rowbase)
{
    int tid = xb * 128 + threadIdx.x;
    int b = tid & (BE - 1);
    int i = rowbase + (tid >> 8);

    const float4* Fr = reinterpret_cast<const float4*>(&g_F[((size_t)i * BE + b) * KK]);
    const float4* Br = reinterpret_cast<const float4*>(&g_B[((size_t)(i + 1) * BE + b) * KK]);

    float Fv[32], Bv[32];
#pragma unroll
    for (int q = 0; q < 8; ++q) {
        float4 f4 = Fr[q];
        Fv[4 * q + 0] = f4.x; Fv[4 * q + 1] = f4.y; Fv[4 * q + 2] = f4.z; Fv[4 * q + 3] = f4.w;
        float4 b4 = Br[q];
        Bv[4 * q + 0] = b4.x; Bv[4 * q + 1] = b4.y; Bv[4 * q + 2] = b4.z; Bv[4 * q + 3] = b4.w;
    }

    float comb[32];
#pragma unroll
    for (int j = 0; j < 32; ++j) {
        float bc = (j == 31) ? 0.0f : Bv[30 - j];   // B[i+1][31-j]; col 0 == 0
        comb[j] = Fv[j] + bc;
    }
    float mx = comb[0];
#pragma unroll
    for (int j = 1; j < 32; ++j) mx = fmaxf(mx, comb[j]);
    float sum = 0.0f;
#pragma unroll
    for (int j = 0; j < 32; ++j) sum += __expf(comb[j] - mx);

    g_S[(size_t)i * BE + b] = g_T[(size_t)i * BE + b] + mx + __logf(sum);
}

// ---------------- sliced fused kernel ----------------
__global__ void k_slice(const float* __restrict__ scores, int s)
{
    if (blockIdx.x < 64) {
        backward_slice(scores, s);
        return;
    }
    int xb = blockIdx.x - 64;
    if (s == 0) {
        if (xb < 2048) phaseA(scores, xb);
        else transpose_theta(scores, xb - 2048);
    } else if (s == 1) {
        if (xb < 64) merge_chunks(xb);
        else samp_chunk(xb - 64, 0);
    } else if (s == 2) {
        if (xb < 2048) phaseC_storeF(scores, xb);
        else samp_chunk(xb - 2048, 1);
    } else if (s == 3) {
        if (xb < 3072) comb_band(xb, 2560);          // rows [2560,4096)
        else samp_chunk(xb - 3072, 2);
    } else {
        // s=4..7: comb rows [4096-512s, 4096-512(s-1)) + sampler chunks band s-1
        if (xb < 1024) comb_band(xb, NN - SLEN * s);
        else samp_chunk(xb - 1024, s - 1);
    }
}

// ---------------- tail: last comb band + last sampler chunk band ----------------
__global__ void k_tail()
{
    if (blockIdx.x < 1024) comb_band(blockIdx.x, 0);   // rows [0, 512)
    else samp_chunk(blockIdx.x - 1024, 7);             // chunks [0,16)
}

// ---------------- finalize ----------------
__global__ void k_final(float* __restrict__ out)
{
    int tid = blockIdx.x * blockDim.x + threadIdx.x;  // 0 .. 2^20-1
    int bz = tid >> 13;
    int rem = tid & 8191;
    int n = rem >> 1;
    int e = rem & 1;
    int be = bz * ENS + e;
    float s = (float)((g_bits[(size_t)be * (NN / 32) + (n >> 5)] >> (n & 31)) & 1u);
    float m = __expf(g_S[(size_t)n * BE + be] - g_logZ[be]);
    out[tid] = (s - m) + m;
    out[HALF_OUT + tid] = m;
}

extern "C" void kernel_launch(void* const* d_in, const int* in_sizes, int n_in,
                              void* d_out, int out_size)
{
    const float* scores = (const float*)d_in[0];
    float* out = (float*)d_out;
    (void)in_sizes; (void)n_in; (void)out_size;

    k_slice<<<64 + 2048 + 2048, 128>>>(scores, 0);  // backward + phaseA + transpose
    k_slice<<<64 + 64 + 1024,   128>>>(scores, 1);  // backward + merge + sampchunk b0
    k_slice<<<64 + 2048 + 1024, 128>>>(scores, 2);  // backward + phaseC + sampchunk b1
    k_slice<<<64 + 3072 + 1024, 128>>>(scores, 3);  // backward + comb [2560,4096) + sc b2
    k_slice<<<64 + 1024 + 1024, 128>>>(scores, 4);  // backward + comb [2048,2560) + sc b3
    k_slice<<<64 + 1024 + 1024, 128>>>(scores, 5);  // backward + comb [1536,2048) + sc b4
    k_slice<<<64 + 1024 + 1024, 128>>>(scores, 6);  // backward + comb [1024,1536) + sc b5
    k_slice<<<64 + 1024 + 1024, 128>>>(scores, 7);  // backward + comb [512,1024)  + sc b6
    k_tail<<<2048, 128>>>();                        // comb [0,512) + sampchunk band7
    k_comp<<<64, 128>>>();                          // sampler state composition
    k_final<<<2048, 512>>>(out);
}